// round 12
// baseline (speedup 1.0000x reference)
#include <cuda_runtime.h>

// ---------------- problem constants ----------------
#define BQ     4
#define CDIM   96
#define HDIM   256
#define WDIM   256
#define HWSZ   65536           // H*W
#define CHW    6291456         // C*H*W
#define NWIN   4096            // B*32*32
#define PADR   66              // padded row stride (even -> 8B-aligned float2 rows)
#define SCALE  0.10206207261596577f   // 96^-0.5

// ---------------- device scratch (static, no allocs) ----------------
__device__ float g_dsx[NWIN * CDIM];
__device__ float g_pv[NWIN * 4 * 3];
__device__ int   g_pi[NWIN * 4 * 3];
__device__ int   g_nidx[NWIN * 3];
__device__ float g_nwt[NWIN * 3];

// ---------------- packed f32x2 helpers ----------------
static __device__ __forceinline__ unsigned long long pk2(float lo, float hi) {
    unsigned long long r;
    asm("mov.b64 %0, {%1, %2};" : "=l"(r) : "f"(lo), "f"(hi));
    return r;
}
static __device__ __forceinline__ void upk2(unsigned long long v, float& lo, float& hi) {
    asm("mov.b64 {%0, %1}, %2;" : "=f"(lo), "=f"(hi) : "l"(v));
}
static __device__ __forceinline__ void fma2(unsigned long long& d,
                                            unsigned long long a,
                                            unsigned long long b) {
    asm("fma.rn.f32x2 %0, %1, %2, %3;" : "=l"(d) : "l"(a), "l"(b), "l"(d));
}

// ==================================================================
// K1: adaptive max pool 8x8 -> dsx[n][c],  n = b*1024 + ghi*32 + gwi
// ==================================================================
__global__ void pool_kernel(const float* __restrict__ x) {
    int bc = blockIdx.x;                 // b*96 + c
    const float* xp = x + (size_t)bc * HWSZ;
    int b = bc / CDIM, c = bc - b * CDIM;
    for (int wi = threadIdx.x; wi < 1024; wi += blockDim.x) {
        int ghi = wi >> 5, gwi = wi & 31;
        const float* base = xp + ghi * 8 * WDIM + gwi * 8;
        float m = -3.402823466e38f;
        #pragma unroll
        for (int r = 0; r < 8; r++) {
            #pragma unroll
            for (int cc = 0; cc < 8; cc++) m = fmaxf(m, base[r * WDIM + cc]);
        }
        g_dsx[(b * 1024 + wi) * CDIM + c] = m;
    }
}

// ==================================================================
// K2: sim GEMM (64 query rows x 1024-col chunk) + stable partial top-3
// grid (64, 4), 256 threads, dyn smem = (2*96*66 + 64*66)*4 = 67584 B
// ==================================================================
__global__ void __launch_bounds__(256, 1) sim_kernel() {
    extern __shared__ float sm[];
    float* AT = sm;                      // [96][66]   query rows, transposed
    float* BT = sm + 96 * PADR;          // [96][66]   key tile, transposed
    float* SS = sm + 2 * 96 * PADR;      // [64][66]   score tile

    int rc = blockIdx.x, chunk = blockIdx.y;
    int tid = threadIdx.x;
    int ty = tid >> 4, tx = tid & 15;

    for (int idx = tid; idx < 64 * 96; idx += 256) {
        int rr = idx / 96, cc = idx - rr * 96;
        AT[cc * PADR + rr] = g_dsx[(rc * 64 + rr) * 96 + cc];
    }

    float v0 = -3.402823466e38f, v1 = v0, v2 = v0;
    int i0 = 0, i1 = 0, i2 = 0;

    for (int t = 0; t < 16; t++) {
        int col0 = chunk * 1024 + t * 64;
        __syncthreads();
        for (int idx = tid; idx < 64 * 96; idx += 256) {
            int rr = idx / 96, cc = idx - rr * 96;
            BT[cc * PADR + rr] = g_dsx[(col0 + rr) * 96 + cc];
        }
        __syncthreads();

        unsigned long long acc[4][2];
        #pragma unroll
        for (int i = 0; i < 4; i++) { acc[i][0] = 0ull; acc[i][1] = 0ull; }

        #pragma unroll 4
        for (int kk = 0; kk < 96; kk++) {
            const float* ar = AT + kk * PADR + 4 * ty;
            const float* br = BT + kk * PADR + 4 * tx;
            unsigned long long b0 = *(const unsigned long long*)(br);
            unsigned long long b1 = *(const unsigned long long*)(br + 2);
            #pragma unroll
            for (int i = 0; i < 4; i++) {
                unsigned long long ap = pk2(ar[i], ar[i]);
                fma2(acc[i][0], ap, b0);
                fma2(acc[i][1], ap, b1);
            }
        }
        #pragma unroll
        for (int i = 0; i < 4; i++) {
            float s0, s1, s2, s3;
            upk2(acc[i][0], s0, s1);
            upk2(acc[i][1], s2, s3);
            float* srow = SS + (4 * ty + i) * PADR + 4 * tx;
            srow[0] = s0; srow[1] = s1; srow[2] = s2; srow[3] = s3;
        }
        __syncthreads();

        if (tid < 64) {
            const float* srow = SS + tid * PADR;
            #pragma unroll 4
            for (int c = 0; c < 64; c++) {
                float s = srow[c];
                int gi = col0 + c;
                if (s > v0)      { v2 = v1; i2 = i1; v1 = v0; i1 = i0; v0 = s; i0 = gi; }
                else if (s > v1) { v2 = v1; i2 = i1; v1 = s; i1 = gi; }
                else if (s > v2) { v2 = s; i2 = gi; }
            }
        }
    }
    if (tid < 64) {
        int row = rc * 64 + tid;
        int o = (row * 4 + chunk) * 3;
        g_pv[o] = v0; g_pv[o + 1] = v1; g_pv[o + 2] = v2;
        g_pi[o] = i0; g_pi[o + 1] = i1; g_pi[o + 2] = i2;
    }
}

// ==================================================================
// K3: merge 4 partial top-3 lists (stable) + softmax weights
// ==================================================================
__global__ void merge_kernel() {
    int r = blockIdx.x * blockDim.x + threadIdx.x;
    if (r >= NWIN) return;
    float cv[12]; int ci[12];
    #pragma unroll
    for (int k = 0; k < 12; k++) { cv[k] = g_pv[r * 12 + k]; ci[k] = g_pi[r * 12 + k]; }
    float bv[3]; int bi[3];
    #pragma unroll
    for (int s = 0; s < 3; s++) {
        int best = 0; float bvv = -3.402823466e38f; int bii = 0x7fffffff;
        #pragma unroll
        for (int k = 0; k < 12; k++) {
            if (ci[k] < 0) continue;
            if (cv[k] > bvv || (cv[k] == bvv && ci[k] < bii)) {
                bvv = cv[k]; bii = ci[k]; best = k;
            }
        }
        bv[s] = bvv; bi[s] = bii; ci[best] = -1;
    }
    float e1 = expf(bv[1] - bv[0]);
    float e2 = expf(bv[2] - bv[0]);
    float inv = 1.f / (1.f + e1 + e2);
    g_nidx[r * 3] = bi[0]; g_nidx[r * 3 + 1] = bi[1]; g_nidx[r * 3 + 2] = bi[2];
    g_nwt[r * 3] = inv;    g_nwt[r * 3 + 1] = e1 * inv; g_nwt[r * 3 + 2] = e2 * inv;
}

// ==================================================================
// K4: fused per-window attention (1 CTA per window)
// ==================================================================
__device__ __forceinline__ void load_w(const float* __restrict__ Wg,
                                       float* __restrict__ sW, int tid) {
    const float4* src = (const float4*)Wg;
    float4* dst = (float4*)sW;
    for (int i = tid; i < 2304; i += 256) dst[i] = __ldg(src + i);
}

// Y[64x96] = A[64x96] @ W[96x96] + bias ; A given transposed [96][66]
template <bool WRITE_T>
__device__ __forceinline__ void gemm96(const float* __restrict__ AT,
                                       const float* __restrict__ Wsm,
                                       const float* __restrict__ bias,
                                       float* __restrict__ outp,
                                       int ty, int tx) {
    unsigned long long acc[4][3];
    {
        float b0 = __ldg(bias + 6 * tx + 0), b1 = __ldg(bias + 6 * tx + 1);
        float b2 = __ldg(bias + 6 * tx + 2), b3 = __ldg(bias + 6 * tx + 3);
        float b4 = __ldg(bias + 6 * tx + 4), b5 = __ldg(bias + 6 * tx + 5);
        unsigned long long p0 = pk2(b0, b1), p1 = pk2(b2, b3), p2 = pk2(b4, b5);
        #pragma unroll
        for (int i = 0; i < 4; i++) { acc[i][0] = p0; acc[i][1] = p1; acc[i][2] = p2; }
    }
    #pragma unroll 4
    for (int kk = 0; kk < 96; kk++) {
        const float* ar = AT + kk * PADR + 4 * ty;
        const float* br = Wsm + kk * 96 + 6 * tx;
        unsigned long long b0 = *(const unsigned long long*)(br);
        unsigned long long b1 = *(const unsigned long long*)(br + 2);
        unsigned long long b2 = *(const unsigned long long*)(br + 4);
        #pragma unroll
        for (int i = 0; i < 4; i++) {
            unsigned long long ap = pk2(ar[i], ar[i]);
            fma2(acc[i][0], ap, b0);
            fma2(acc[i][1], ap, b1);
            fma2(acc[i][2], ap, b2);
        }
    }
    #pragma unroll
    for (int i = 0; i < 4; i++) {
        float v[6];
        upk2(acc[i][0], v[0], v[1]);
        upk2(acc[i][1], v[2], v[3]);
        upk2(acc[i][2], v[4], v[5]);
        int p = 4 * ty + i;
        #pragma unroll
        for (int j = 0; j < 6; j++) {
            int c = 6 * tx + j;
            if (WRITE_T) outp[c * PADR + p] = v[j];
            else         outp[p * 96 + c] = v[j];
        }
    }
}

// S[64x64] = Q @ K^T * scale ; Q,K transposed [96][66]
__device__ __forceinline__ void gemm_qk(const float* __restrict__ QT,
                                        const float* __restrict__ KT,
                                        float* __restrict__ S,
                                        int ty, int tx) {
    unsigned long long acc[4][2];
    #pragma unroll
    for (int i = 0; i < 4; i++) { acc[i][0] = 0ull; acc[i][1] = 0ull; }
    #pragma unroll 4
    for (int kk = 0; kk < 96; kk++) {
        const float* ar = QT + kk * PADR + 4 * ty;
        const float* br = KT + kk * PADR + 4 * tx;
        unsigned long long b0 = *(const unsigned long long*)(br);
        unsigned long long b1 = *(const unsigned long long*)(br + 2);
        #pragma unroll
        for (int i = 0; i < 4; i++) {
            unsigned long long ap = pk2(ar[i], ar[i]);
            fma2(acc[i][0], ap, b0);
            fma2(acc[i][1], ap, b1);
        }
    }
    #pragma unroll
    for (int i = 0; i < 4; i++) {
        float s0, s1, s2, s3;
        upk2(acc[i][0], s0, s1);
        upk2(acc[i][1], s2, s3);
        float* srow = S + (4 * ty + i) * PADR + 4 * tx;
        srow[0] = s0 * SCALE; srow[1] = s1 * SCALE;
        srow[2] = s2 * SCALE; srow[3] = s3 * SCALE;
    }
}

// O[64x96] = attn[64x64] @ V[64x96] + lepe ; attn transposed [64][66], V natural
__device__ __forceinline__ void gemm_pv(const float* __restrict__ ST,
                                        const float* __restrict__ V,
                                        const float* __restrict__ LP,
                                        float* __restrict__ OT,
                                        int ty, int tx) {
    unsigned long long acc[4][3];
    #pragma unroll
    for (int i = 0; i < 4; i++) { acc[i][0] = 0ull; acc[i][1] = 0ull; acc[i][2] = 0ull; }
    #pragma unroll 4
    for (int kk = 0; kk < 64; kk++) {
        const float* ar = ST + kk * PADR + 4 * ty;
        const float* br = V + kk * 96 + 6 * tx;
        unsigned long long b0 = *(const unsigned long long*)(br);
        unsigned long long b1 = *(const unsigned long long*)(br + 2);
        unsigned long long b2 = *(const unsigned long long*)(br + 4);
        #pragma unroll
        for (int i = 0; i < 4; i++) {
            unsigned long long ap = pk2(ar[i], ar[i]);
            fma2(acc[i][0], ap, b0);
            fma2(acc[i][1], ap, b1);
            fma2(acc[i][2], ap, b2);
        }
    }
    #pragma unroll
    for (int i = 0; i < 4; i++) {
        float v[6];
        upk2(acc[i][0], v[0], v[1]);
        upk2(acc[i][1], v[2], v[3]);
        upk2(acc[i][2], v[4], v[5]);
        int p = 4 * ty + i;
        #pragma unroll
        for (int j = 0; j < 6; j++) {
            int c = 6 * tx + j;
            OT[c * PADR + p] = v[j] + LP[c * PADR + p];
        }
    }
}

__global__ void __launch_bounds__(256, 1) attn_kernel(
    const float* __restrict__ x,
    const float* __restrict__ Wq, const float* __restrict__ bq,
    const float* __restrict__ Wk, const float* __restrict__ bk,
    const float* __restrict__ Wv, const float* __restrict__ bv,
    const float* __restrict__ Wp, const float* __restrict__ bp,
    const float* __restrict__ lw, const float* __restrict__ lb,
    float* __restrict__ out) {
    extern __shared__ float sm[];
    float* sXWT  = sm;               // [96][66] window, transposed (later: O^T)
    float* sCTXT = sm + 6336;        // [96][66] context (later: lepe, then Y^T)
    float* sQT   = sm + 12672;       // [96][66]
    float* sKT   = sm + 19008;       // [96][66]
    float* sV    = sm + 25344;       // [64][96] natural
    float* sS    = sm + 31488;       // [64][66] scores (first: lepe weights stage)
    float* sST   = sm + 35712;       // [64][66] probs transposed
    float* sW    = sm + 39936;       // [96][96] staged weight matrix

    int n = blockIdx.x;
    int tid = threadIdx.x, ty = tid >> 4, tx = tid & 15;
    int b = n >> 10, wi = n & 1023;
    const float* xwin = x + (size_t)b * CHW + (wi >> 5) * (8 * WDIM) + (wi & 31) * 8;

    float w0 = g_nwt[n * 3], w1 = g_nwt[n * 3 + 1], w2 = g_nwt[n * 3 + 2];
    int m0 = g_nidx[n * 3], m1 = g_nidx[n * 3 + 1], m2 = g_nidx[n * 3 + 2];
    const float* nb0 = x + (size_t)(m0 >> 10) * CHW + ((m0 & 1023) >> 5) * (8 * WDIM) + (m0 & 31) * 8;
    const float* nb1 = x + (size_t)(m1 >> 10) * CHW + ((m1 & 1023) >> 5) * (8 * WDIM) + (m1 & 31) * 8;
    const float* nb2 = x + (size_t)(m2 >> 10) * CHW + ((m2 & 1023) >> 5) * (8 * WDIM) + (m2 & 31) * 8;

    // stage lepe weights+bias into sS (free until gemm_qk)
    for (int i = tid; i < 960; i += 256)
        sS[i] = (i < 864) ? __ldg(lw + i) : __ldg(lb + (i - 864));

    // load window (transposed) + weighted neighbor gather (context)
    for (int idx = tid; idx < 6144; idx += 256) {
        int c = idx >> 6, p = idx & 63;
        int off = c * HWSZ + (p >> 3) * WDIM + (p & 7);
        sXWT[c * PADR + p] = __ldg(xwin + off);
        sCTXT[c * PADR + p] = w0 * __ldg(nb0 + off) + w1 * __ldg(nb1 + off) + w2 * __ldg(nb2 + off);
    }
    load_w(Wq, sW, tid);
    __syncthreads();

    gemm96<true>(sXWT, sW, bq, sQT, ty, tx);       // Q^T
    __syncthreads();
    load_w(Wk, sW, tid);
    __syncthreads();
    gemm96<true>(sCTXT, sW, bk, sKT, ty, tx);      // K^T
    __syncthreads();
    load_w(Wv, sW, tid);
    __syncthreads();
    gemm96<false>(sCTXT, sW, bv, sV, ty, tx);      // V natural
    __syncthreads();

    // lepe: per-window zero-padded depthwise 3x3 (weights staged in sS) -> sCTXT
    for (int idx = tid; idx < 6144; idx += 256) {
        int c = idx >> 6, p = idx & 63, rr = p >> 3, cc = p & 7;
        const float* img = sXWT + c * PADR;
        const float* wk = sS + c * 9;
        float a = sS[864 + c];
        #pragma unroll
        for (int ky = 0; ky < 3; ky++) {
            int r2 = rr + ky - 1;
            if (r2 < 0 || r2 > 7) continue;
            #pragma unroll
            for (int kx = 0; kx < 3; kx++) {
                int c2 = cc + kx - 1;
                if (c2 < 0 || c2 > 7) continue;
                a += wk[ky * 3 + kx] * img[r2 * 8 + c2];
            }
        }
        sCTXT[c * PADR + p] = a;
    }
    __syncthreads();   // lepe reads of sS done before gemm_qk overwrites it

    gemm_qk(sQT, sKT, sS, ty, tx);                 // scores
    __syncthreads();

    // row softmax: quad of 4 threads per row, 16 cols each
    {
        int r = tid >> 2, q = tid & 3;
        const float* row = sS + r * PADR + q * 16;
        float m = -3.402823466e38f;
        #pragma unroll
        for (int c2 = 0; c2 < 16; c2++) m = fmaxf(m, row[c2]);
        m = fmaxf(m, __shfl_xor_sync(0xffffffffu, m, 1));
        m = fmaxf(m, __shfl_xor_sync(0xffffffffu, m, 2));
        float e[16]; float ssum = 0.f;
        #pragma unroll
        for (int c2 = 0; c2 < 16; c2++) { e[c2] = __expf(row[c2] - m); ssum += e[c2]; }
        ssum += __shfl_xor_sync(0xffffffffu, ssum, 1);
        ssum += __shfl_xor_sync(0xffffffffu, ssum, 2);
        float inv = 1.f / ssum;
        #pragma unroll
        for (int c2 = 0; c2 < 16; c2++) sST[(q * 16 + c2) * PADR + r] = e[c2] * inv;
    }
    __syncthreads();

    gemm_pv(sST, sV, sCTXT, sXWT, ty, tx);         // O^T = attn@V + lepe
    __syncthreads();
    load_w(Wp, sW, tid);
    __syncthreads();
    gemm96<true>(sXWT, sW, bp, sCTXT, ty, tx);     // Y^T
    __syncthreads();

    float* owin = out + (size_t)b * CHW + (wi >> 5) * (8 * WDIM) + (wi & 31) * 8;
    for (int idx = tid; idx < 6144; idx += 256) {
        int c = idx >> 6, p = idx & 63;
        owin[c * HWSZ + (p >> 3) * WDIM + (p & 7)] = sCTXT[c * PADR + p];
    }
}

// ==================================================================
// launch
// ==================================================================
extern "C" void kernel_launch(void* const* d_in, const int* in_sizes, int n_in,
                              void* d_out, int out_size) {
    const float* x  = (const float*)d_in[0];
    const float* Wq = (const float*)d_in[1];
    const float* bq = (const float*)d_in[2];
    const float* Wk = (const float*)d_in[3];
    const float* bk = (const float*)d_in[4];
    const float* Wv = (const float*)d_in[5];
    const float* bv = (const float*)d_in[6];
    const float* Wp = (const float*)d_in[7];
    const float* bp = (const float*)d_in[8];
    const float* lw = (const float*)d_in[9];
    const float* lb = (const float*)d_in[10];
    float* out = (float*)d_out;

    pool_kernel<<<BQ * CDIM, 256>>>(x);

    size_t sm2 = (size_t)(2 * 96 * PADR + 64 * PADR) * sizeof(float);   // 67584
    cudaFuncSetAttribute(sim_kernel, cudaFuncAttributeMaxDynamicSharedMemorySize, (int)sm2);
    sim_kernel<<<dim3(64, 4), 256, sm2>>>();

    merge_kernel<<<NWIN / 256, 256>>>();

    size_t sm4 = (size_t)49152 * sizeof(float);                          // 196608
    cudaFuncSetAttribute(attn_kernel, cudaFuncAttributeMaxDynamicSharedMemorySize, (int)sm4);
    attn_kernel<<<NWIN, 256, sm4>>>(x, Wq, bq, Wk, bk, Wv, bv, Wp, bp, lw, lb, out);
}

// round 13
// speedup vs baseline: 1.0028x; 1.0028x over previous
#include <cuda_runtime.h>

// ---------------- problem constants ----------------
#define BQ     4
#define CDIM   96
#define HDIM   256
#define WDIM   256
#define HWSZ   65536           // H*W
#define CHW    6291456         // C*H*W
#define NWIN   4096            // B*32*32
#define PADR   66              // padded row stride (even -> 8B-aligned float2 rows)
#define SCALE  0.10206207261596577f   // 96^-0.5

// ---------------- device scratch (static, no allocs) ----------------
__device__ float g_dsx[NWIN * CDIM];
__device__ float g_pv[NWIN * 4 * 3];
__device__ int   g_pi[NWIN * 4 * 3];
__device__ int   g_nidx[NWIN * 3];
__device__ float g_nwt[NWIN * 3];

// ---------------- packed f32x2 helpers ----------------
static __device__ __forceinline__ unsigned long long pk2(float lo, float hi) {
    unsigned long long r;
    asm("mov.b64 %0, {%1, %2};" : "=l"(r) : "f"(lo), "f"(hi));
    return r;
}
static __device__ __forceinline__ void upk2(unsigned long long v, float& lo, float& hi) {
    asm("mov.b64 {%0, %1}, %2;" : "=f"(lo), "=f"(hi) : "l"(v));
}
static __device__ __forceinline__ void fma2(unsigned long long& d,
                                            unsigned long long a,
                                            unsigned long long b) {
    asm("fma.rn.f32x2 %0, %1, %2, %3;" : "=l"(d) : "l"(a), "l"(b), "l"(d));
}

// ==================================================================
// K1: adaptive max pool 8x8 -> dsx[n][c],  n = b*1024 + ghi*32 + gwi
// ==================================================================
__global__ void pool_kernel(const float* __restrict__ x) {
    int bc = blockIdx.x;                 // b*96 + c
    const float* xp = x + (size_t)bc * HWSZ;
    int b = bc / CDIM, c = bc - b * CDIM;
    for (int wi = threadIdx.x; wi < 1024; wi += blockDim.x) {
        int ghi = wi >> 5, gwi = wi & 31;
        const float* base = xp + ghi * 8 * WDIM + gwi * 8;
        float m = -3.402823466e38f;
        #pragma unroll
        for (int r = 0; r < 8; r++) {
            #pragma unroll
            for (int cc = 0; cc < 8; cc++) m = fmaxf(m, base[r * WDIM + cc]);
        }
        g_dsx[(b * 1024 + wi) * CDIM + c] = m;
    }
}

// ==================================================================
// K2: sim GEMM (64 query rows x 1024-col chunk) + stable partial top-3
// grid (64, 4), 256 threads, dyn smem = (2*96*66 + 64*66)*4 = 67584 B
// ==================================================================
__global__ void __launch_bounds__(256, 1) sim_kernel() {
    extern __shared__ float sm[];
    float* AT = sm;                      // [96][66]   query rows, transposed
    float* BT = sm + 96 * PADR;          // [96][66]   key tile, transposed
    float* SS = sm + 2 * 96 * PADR;      // [64][66]   score tile

    int rc = blockIdx.x, chunk = blockIdx.y;
    int tid = threadIdx.x;
    int ty = tid >> 4, tx = tid & 15;

    for (int idx = tid; idx < 64 * 96; idx += 256) {
        int rr = idx / 96, cc = idx - rr * 96;
        AT[cc * PADR + rr] = g_dsx[(rc * 64 + rr) * 96 + cc];
    }

    float v0 = -3.402823466e38f, v1 = v0, v2 = v0;
    int i0 = 0, i1 = 0, i2 = 0;

    for (int t = 0; t < 16; t++) {
        int col0 = chunk * 1024 + t * 64;
        __syncthreads();
        for (int idx = tid; idx < 64 * 96; idx += 256) {
            int rr = idx / 96, cc = idx - rr * 96;
            BT[cc * PADR + rr] = g_dsx[(col0 + rr) * 96 + cc];
        }
        __syncthreads();

        unsigned long long acc[4][2];
        #pragma unroll
        for (int i = 0; i < 4; i++) { acc[i][0] = 0ull; acc[i][1] = 0ull; }

        #pragma unroll 4
        for (int kk = 0; kk < 96; kk++) {
            const float* ar = AT + kk * PADR + 4 * ty;
            const float* br = BT + kk * PADR + 4 * tx;
            unsigned long long b0 = *(const unsigned long long*)(br);
            unsigned long long b1 = *(const unsigned long long*)(br + 2);
            #pragma unroll
            for (int i = 0; i < 4; i++) {
                unsigned long long ap = pk2(ar[i], ar[i]);
                fma2(acc[i][0], ap, b0);
                fma2(acc[i][1], ap, b1);
            }
        }
        #pragma unroll
        for (int i = 0; i < 4; i++) {
            float s0, s1, s2, s3;
            upk2(acc[i][0], s0, s1);
            upk2(acc[i][1], s2, s3);
            float* srow = SS + (4 * ty + i) * PADR + 4 * tx;
            srow[0] = s0; srow[1] = s1; srow[2] = s2; srow[3] = s3;
        }
        __syncthreads();

        if (tid < 64) {
            const float* srow = SS + tid * PADR;
            #pragma unroll 4
            for (int c = 0; c < 64; c++) {
                float s = srow[c];
                int gi = col0 + c;
                if (s > v0)      { v2 = v1; i2 = i1; v1 = v0; i1 = i0; v0 = s; i0 = gi; }
                else if (s > v1) { v2 = v1; i2 = i1; v1 = s; i1 = gi; }
                else if (s > v2) { v2 = s; i2 = gi; }
            }
        }
    }
    if (tid < 64) {
        int row = rc * 64 + tid;
        int o = (row * 4 + chunk) * 3;
        g_pv[o] = v0; g_pv[o + 1] = v1; g_pv[o + 2] = v2;
        g_pi[o] = i0; g_pi[o + 1] = i1; g_pi[o + 2] = i2;
    }
}

// ==================================================================
// K3: merge 4 partial top-3 lists (stable) + softmax weights
// ==================================================================
__global__ void merge_kernel() {
    int r = blockIdx.x * blockDim.x + threadIdx.x;
    if (r >= NWIN) return;
    float cv[12]; int ci[12];
    #pragma unroll
    for (int k = 0; k < 12; k++) { cv[k] = g_pv[r * 12 + k]; ci[k] = g_pi[r * 12 + k]; }
    float bv[3]; int bi[3];
    #pragma unroll
    for (int s = 0; s < 3; s++) {
        int best = 0; float bvv = -3.402823466e38f; int bii = 0x7fffffff;
        #pragma unroll
        for (int k = 0; k < 12; k++) {
            if (ci[k] < 0) continue;
            if (cv[k] > bvv || (cv[k] == bvv && ci[k] < bii)) {
                bvv = cv[k]; bii = ci[k]; best = k;
            }
        }
        bv[s] = bvv; bi[s] = bii; ci[best] = -1;
    }
    float e1 = expf(bv[1] - bv[0]);
    float e2 = expf(bv[2] - bv[0]);
    float inv = 1.f / (1.f + e1 + e2);
    g_nidx[r * 3] = bi[0]; g_nidx[r * 3 + 1] = bi[1]; g_nidx[r * 3 + 2] = bi[2];
    g_nwt[r * 3] = inv;    g_nwt[r * 3 + 1] = e1 * inv; g_nwt[r * 3 + 2] = e2 * inv;
}

// ==================================================================
// K4: fused per-window attention (1 CTA per window)
// ==================================================================
__device__ __forceinline__ void load_w(const float* __restrict__ Wg,
                                       float* __restrict__ sW, int tid) {
    const float4* src = (const float4*)Wg;
    float4* dst = (float4*)sW;
    for (int i = tid; i < 2304; i += 256) dst[i] = __ldg(src + i);
}

// Y[64x96] = A[64x96] @ W[96x96] + bias ; A given transposed [96][66]
template <bool WRITE_T>
__device__ __forceinline__ void gemm96(const float* __restrict__ AT,
                                       const float* __restrict__ Wsm,
                                       const float* __restrict__ bias,
                                       float* __restrict__ outp,
                                       int ty, int tx) {
    unsigned long long acc[4][3];
    {
        float b0 = __ldg(bias + 6 * tx + 0), b1 = __ldg(bias + 6 * tx + 1);
        float b2 = __ldg(bias + 6 * tx + 2), b3 = __ldg(bias + 6 * tx + 3);
        float b4 = __ldg(bias + 6 * tx + 4), b5 = __ldg(bias + 6 * tx + 5);
        unsigned long long p0 = pk2(b0, b1), p1 = pk2(b2, b3), p2 = pk2(b4, b5);
        #pragma unroll
        for (int i = 0; i < 4; i++) { acc[i][0] = p0; acc[i][1] = p1; acc[i][2] = p2; }
    }
    #pragma unroll 4
    for (int kk = 0; kk < 96; kk++) {
        const float* ar = AT + kk * PADR + 4 * ty;
        const float* br = Wsm + kk * 96 + 6 * tx;
        unsigned long long b0 = *(const unsigned long long*)(br);
        unsigned long long b1 = *(const unsigned long long*)(br + 2);
        unsigned long long b2 = *(const unsigned long long*)(br + 4);
        #pragma unroll
        for (int i = 0; i < 4; i++) {
            unsigned long long ap = pk2(ar[i], ar[i]);
            fma2(acc[i][0], ap, b0);
            fma2(acc[i][1], ap, b1);
            fma2(acc[i][2], ap, b2);
        }
    }
    #pragma unroll
    for (int i = 0; i < 4; i++) {
        float v[6];
        upk2(acc[i][0], v[0], v[1]);
        upk2(acc[i][1], v[2], v[3]);
        upk2(acc[i][2], v[4], v[5]);
        int p = 4 * ty + i;
        #pragma unroll
        for (int j = 0; j < 6; j++) {
            int c = 6 * tx + j;
            if (WRITE_T) outp[c * PADR + p] = v[j];
            else         outp[p * 96 + c] = v[j];
        }
    }
}

// S[64x64] = Q @ K^T * scale ; Q,K transposed [96][66]
__device__ __forceinline__ void gemm_qk(const float* __restrict__ QT,
                                        const float* __restrict__ KT,
                                        float* __restrict__ S,
                                        int ty, int tx) {
    unsigned long long acc[4][2];
    #pragma unroll
    for (int i = 0; i < 4; i++) { acc[i][0] = 0ull; acc[i][1] = 0ull; }
    #pragma unroll 4
    for (int kk = 0; kk < 96; kk++) {
        const float* ar = QT + kk * PADR + 4 * ty;
        const float* br = KT + kk * PADR + 4 * tx;
        unsigned long long b0 = *(const unsigned long long*)(br);
        unsigned long long b1 = *(const unsigned long long*)(br + 2);
        #pragma unroll
        for (int i = 0; i < 4; i++) {
            unsigned long long ap = pk2(ar[i], ar[i]);
            fma2(acc[i][0], ap, b0);
            fma2(acc[i][1], ap, b1);
        }
    }
    #pragma unroll
    for (int i = 0; i < 4; i++) {
        float s0, s1, s2, s3;
        upk2(acc[i][0], s0, s1);
        upk2(acc[i][1], s2, s3);
        float* srow = S + (4 * ty + i) * PADR + 4 * tx;
        srow[0] = s0 * SCALE; srow[1] = s1 * SCALE;
        srow[2] = s2 * SCALE; srow[3] = s3 * SCALE;
    }
}

// O[64x96] = attn[64x64] @ V[64x96] + lepe ; attn transposed [64][66], V natural
__device__ __forceinline__ void gemm_pv(const float* __restrict__ ST,
                                        const float* __restrict__ V,
                                        const float* __restrict__ LP,
                                        float* __restrict__ OT,
                                        int ty, int tx) {
    unsigned long long acc[4][3];
    #pragma unroll
    for (int i = 0; i < 4; i++) { acc[i][0] = 0ull; acc[i][1] = 0ull; acc[i][2] = 0ull; }
    #pragma unroll 4
    for (int kk = 0; kk < 64; kk++) {
        const float* ar = ST + kk * PADR + 4 * ty;
        const float* br = V + kk * 96 + 6 * tx;
        unsigned long long b0 = *(const unsigned long long*)(br);
        unsigned long long b1 = *(const unsigned long long*)(br + 2);
        unsigned long long b2 = *(const unsigned long long*)(br + 4);
        #pragma unroll
        for (int i = 0; i < 4; i++) {
            unsigned long long ap = pk2(ar[i], ar[i]);
            fma2(acc[i][0], ap, b0);
            fma2(acc[i][1], ap, b1);
            fma2(acc[i][2], ap, b2);
        }
    }
    #pragma unroll
    for (int i = 0; i < 4; i++) {
        float v[6];
        upk2(acc[i][0], v[0], v[1]);
        upk2(acc[i][1], v[2], v[3]);
        upk2(acc[i][2], v[4], v[5]);
        int p = 4 * ty + i;
        #pragma unroll
        for (int j = 0; j < 6; j++) {
            int c = 6 * tx + j;
            OT[c * PADR + p] = v[j] + LP[c * PADR + p];
        }
    }
}

__global__ void __launch_bounds__(256, 1) attn_kernel(
    const float* __restrict__ x,
    const float* __restrict__ Wq, const float* __restrict__ bq,
    const float* __restrict__ Wk, const float* __restrict__ bk,
    const float* __restrict__ Wv, const float* __restrict__ bv,
    const float* __restrict__ Wp, const float* __restrict__ bp,
    const float* __restrict__ lw, const float* __restrict__ lb,
    float* __restrict__ out) {
    extern __shared__ float sm[];
    float* sXWT  = sm;               // [96][66] window, transposed (later: O^T)
    float* sCTXT = sm + 6336;        // [96][66] context (later: lepe, then Y^T)
    float* sQT   = sm + 12672;       // [96][66]
    float* sKT   = sm + 19008;       // [96][66]
    float* sV    = sm + 25344;       // [64][96] natural
    float* sS    = sm + 31488;       // [64][66] scores (first: lepe weights stage)
    float* sST   = sm + 35712;       // [64][66] probs transposed
    float* sW    = sm + 39936;       // [96][96] staged weight matrix

    int n = blockIdx.x;
    int tid = threadIdx.x, ty = tid >> 4, tx = tid & 15;
    int b = n >> 10, wi = n & 1023;
    const float* xwin = x + (size_t)b * CHW + (wi >> 5) * (8 * WDIM) + (wi & 31) * 8;

    float w0 = g_nwt[n * 3], w1 = g_nwt[n * 3 + 1], w2 = g_nwt[n * 3 + 2];
    int m0 = g_nidx[n * 3], m1 = g_nidx[n * 3 + 1], m2 = g_nidx[n * 3 + 2];
    const float* nb0 = x + (size_t)(m0 >> 10) * CHW + ((m0 & 1023) >> 5) * (8 * WDIM) + (m0 & 31) * 8;
    const float* nb1 = x + (size_t)(m1 >> 10) * CHW + ((m1 & 1023) >> 5) * (8 * WDIM) + (m1 & 31) * 8;
    const float* nb2 = x + (size_t)(m2 >> 10) * CHW + ((m2 & 1023) >> 5) * (8 * WDIM) + (m2 & 31) * 8;

    // stage lepe weights+bias into sS (free until gemm_qk)
    for (int i = tid; i < 960; i += 256)
        sS[i] = (i < 864) ? __ldg(lw + i) : __ldg(lb + (i - 864));

    // load window (transposed) + weighted neighbor gather (context)
    for (int idx = tid; idx < 6144; idx += 256) {
        int c = idx >> 6, p = idx & 63;
        int off = c * HWSZ + (p >> 3) * WDIM + (p & 7);
        sXWT[c * PADR + p] = __ldg(xwin + off);
        sCTXT[c * PADR + p] = w0 * __ldg(nb0 + off) + w1 * __ldg(nb1 + off) + w2 * __ldg(nb2 + off);
    }
    load_w(Wq, sW, tid);
    __syncthreads();

    gemm96<true>(sXWT, sW, bq, sQT, ty, tx);       // Q^T
    __syncthreads();
    load_w(Wk, sW, tid);
    __syncthreads();
    gemm96<true>(sCTXT, sW, bk, sKT, ty, tx);      // K^T
    __syncthreads();
    load_w(Wv, sW, tid);
    __syncthreads();
    gemm96<false>(sCTXT, sW, bv, sV, ty, tx);      // V natural
    __syncthreads();

    // lepe: per-window zero-padded depthwise 3x3 (weights staged in sS) -> sCTXT
    for (int idx = tid; idx < 6144; idx += 256) {
        int c = idx >> 6, p = idx & 63, rr = p >> 3, cc = p & 7;
        const float* img = sXWT + c * PADR;
        const float* wk = sS + c * 9;
        float a = sS[864 + c];
        #pragma unroll
        for (int ky = 0; ky < 3; ky++) {
            int r2 = rr + ky - 1;
            if (r2 < 0 || r2 > 7) continue;
            #pragma unroll
            for (int kx = 0; kx < 3; kx++) {
                int c2 = cc + kx - 1;
                if (c2 < 0 || c2 > 7) continue;
                a += wk[ky * 3 + kx] * img[r2 * 8 + c2];
            }
        }
        sCTXT[c * PADR + p] = a;
    }
    __syncthreads();   // lepe reads of sS done before gemm_qk overwrites it

    gemm_qk(sQT, sKT, sS, ty, tx);                 // scores
    __syncthreads();

    // row softmax: quad of 4 threads per row, 16 cols each
    {
        int r = tid >> 2, q = tid & 3;
        const float* row = sS + r * PADR + q * 16;
        float m = -3.402823466e38f;
        #pragma unroll
        for (int c2 = 0; c2 < 16; c2++) m = fmaxf(m, row[c2]);
        m = fmaxf(m, __shfl_xor_sync(0xffffffffu, m, 1));
        m = fmaxf(m, __shfl_xor_sync(0xffffffffu, m, 2));
        float e[16]; float ssum = 0.f;
        #pragma unroll
        for (int c2 = 0; c2 < 16; c2++) { e[c2] = __expf(row[c2] - m); ssum += e[c2]; }
        ssum += __shfl_xor_sync(0xffffffffu, ssum, 1);
        ssum += __shfl_xor_sync(0xffffffffu, ssum, 2);
        float inv = 1.f / ssum;
        #pragma unroll
        for (int c2 = 0; c2 < 16; c2++) sST[(q * 16 + c2) * PADR + r] = e[c2] * inv;
    }
    __syncthreads();

    gemm_pv(sST, sV, sCTXT, sXWT, ty, tx);         // O^T = attn@V + lepe
    __syncthreads();
    load_w(Wp, sW, tid);
    __syncthreads();
    gemm96<true>(sXWT, sW, bp, sCTXT, ty, tx);     // Y^T
    __syncthreads();

    float* owin = out + (size_t)b * CHW + (wi >> 5) * (8 * WDIM) + (wi & 31) * 8;
    for (int idx = tid; idx < 6144; idx += 256) {
        int c = idx >> 6, p = idx & 63;
        owin[c * HWSZ + (p >> 3) * WDIM + (p & 7)] = sCTXT[c * PADR + p];
    }
}

// ==================================================================
// launch
// ==================================================================
extern "C" void kernel_launch(void* const* d_in, const int* in_sizes, int n_in,
                              void* d_out, int out_size) {
    const float* x  = (const float*)d_in[0];
    const float* Wq = (const float*)d_in[1];
    const float* bq = (const float*)d_in[2];
    const float* Wk = (const float*)d_in[3];
    const float* bk = (const float*)d_in[4];
    const float* Wv = (const float*)d_in[5];
    const float* bv = (const float*)d_in[6];
    const float* Wp = (const float*)d_in[7];
    const float* bp = (const float*)d_in[8];
    const float* lw = (const float*)d_in[9];
    const float* lb = (const float*)d_in[10];
    float* out = (float*)d_out;

    pool_kernel<<<BQ * CDIM, 256>>>(x);

    size_t sm2 = (size_t)(2 * 96 * PADR + 64 * PADR) * sizeof(float);   // 67584
    cudaFuncSetAttribute(sim_kernel, cudaFuncAttributeMaxDynamicSharedMemorySize, (int)sm2);
    sim_kernel<<<dim3(64, 4), 256, sm2>>>();

    merge_kernel<<<NWIN / 256, 256>>>();

    size_t sm4 = (size_t)49152 * sizeof(float);                          // 196608
    cudaFuncSetAttribute(attn_kernel, cudaFuncAttributeMaxDynamicSharedMemorySize, (int)sm4);
    attn_kernel<<<NWIN, 256, sm4>>>(x, Wq, bq, Wk, bk, Wv, bv, Wp, bp, lw, lb, out);
}